// round 10
// baseline (speedup 1.0000x reference)
#include <cuda_runtime.h>
#include <math.h>
#include <stdint.h>

#define EPSF 1e-5f

// packed fp32x2 FMA (SASS FFMA2) — only reachable via PTX
#define FFMA2(d,a,b,c) asm("fma.rn.f32x2 %0, %1, %2, %3;" \
                           : "=l"(d) : "l"(a), "l"(b), "l"(c))
#define UNPACK2(lo,hi,p) asm("mov.b64 {%0, %1}, %2;" : "=f"(lo), "=f"(hi) : "l"(p))

// ---------------- small scratch (no allocs allowed) ----------------
__device__ float  g_diag[16 * 512 * 64];   // (n,t,h)  2 MB
__device__ float2 g_Wd[64 * 9 * 64];       // dup'd conv weights [(op*9+k)*64+o] = {w,w}
__device__ int    g_eraw[16 * 512];        // decoded edges (n,2,e)  32 KB

// ---------------- kernel 0: dtype-robust edge decode (int32 OR int64) --------
__global__ void edge_decode_kernel(const int* __restrict__ raw) {
    int tid = threadIdx.x;                 // 1024 threads, 1 block
    int acc = 0;
    for (int i = tid; i < 4096; i += 1024) acc |= raw[2 * i + 1];
    int any_odd = __syncthreads_or(acc != 0);
    bool is64 = (any_odd == 0);
    for (int i = tid; i < 8192; i += 1024)
        g_eraw[i] = is64 ? raw[2 * i] : raw[i];
}

// ---------------- kernel 1: dup-pack W_tcn -> float2 [(op*9+k)][o] -----------
__global__ void wt_kernel(const float* __restrict__ W) {   // W[o][o'][k][1]
    int idx = blockIdx.x * blockDim.x + threadIdx.x;       // 64*9*64 = 36864
    if (idx >= 64 * 9 * 64) return;
    int o = idx & 63;
    int r = idx >> 6;           // op*9 + k
    int k = r % 9, op = r / 9;
    float w = W[(size_t)o * 576 + op * 9 + k];
    g_Wd[idx] = make_float2(w, w);
}

// ---------------- kernel 2: attention diag (edge-scan, atomic-free) ----------
__global__ void diag_kernel(const float* __restrict__ X,
                            const float* __restrict__ w1, const float* __restrict__ b1p,
                            const float* __restrict__ w2, const float* __restrict__ b2p) {
    int nt = blockIdx.x;          // 0..8191
    int n = nt >> 9;
    int h = threadIdx.x;

    __shared__ float sa1[64], sw1[64], sw2[64];
    __shared__ int   se[256];
    sw1[h] = w1[h];
    sw2[h] = w2[h];
    const int* ep = g_eraw + n * 512;
#pragma unroll
    for (int i = 0; i < 4; i++) {
        int e = h + i * 64;
        se[e] = ep[e] * 64 + ep[256 + e];
    }
    __syncthreads();

    const float4* xp = (const float4*)(X + ((size_t)nt * 64 + h) * 64);
    float d1 = 0.f, d2 = 0.f;
#pragma unroll
    for (int c4 = 0; c4 < 16; c4++) {
        float4 x = xp[c4];
        d1 += x.x * sw1[c4 * 4 + 0] + x.y * sw1[c4 * 4 + 1]
            + x.z * sw1[c4 * 4 + 2] + x.w * sw1[c4 * 4 + 3];
        d2 += x.x * sw2[c4 * 4 + 0] + x.y * sw2[c4 * 4 + 1]
            + x.z * sw2[c4 * 4 + 2] + x.w * sw2[c4 * 4 + 3];
    }
    sa1[h] = d1 + b1p[0];
    float a2h = d2 + b2p[0];
    __syncthreads();

    float den = 0.f;
#pragma unroll 8
    for (int k = 0; k < 64; k++) {
        float v = sa1[k] + a2h;
        v = (v > 0.f) ? v : 0.01f * v;
        den += __expf(v);
    }
    float num = 0.f;
    for (int i = 0; i < 256; i++) {
        int rc = se[i];
        if ((rc >> 6) == h) {
            float v = sa1[rc & 63] + a2h;
            v = (v > 0.f) ? v : 0.01f * v;
            num += __expf(v);
        }
    }
    g_diag[(size_t)nt * 64 + h] = num / den + 1.f;
}

// ---------------- kernel 3: FUSED support GEMM + bn1 + relu + temporal conv
//                  + bias + bn2 + residual + relu — packed f32x2 math ---------
// block: one (n,h) x a tile of 64 t's. 256 threads = 64 o x 4 t-groups.
// bufA: X tile [72 rows][64 ch]  ->  y1 transposed [64 o][76]
// bufB: Ws [64 o][68]            ->  S = y1 shifted by +1 row [64 o][76]
__global__ void __launch_bounds__(256, 3)
fused_kernel(const float* __restrict__ X,
             const float* __restrict__ Wl, const float* __restrict__ bl,
             const float* __restrict__ g1, const float* __restrict__ be1,
             const float* __restrict__ bt,
             const float* __restrict__ g2, const float* __restrict__ be2,
             float* __restrict__ out) {
    __shared__ float bufA[64 * 76];
    __shared__ float bufB[64 * 76];

    int bid = blockIdx.x;             // 0..8191
    int tb = bid & 7;
    int nh = bid >> 3;
    int n = nh >> 6, h = nh & 63;
    int t0 = tb * 64;
    int tid = threadIdx.x;

    // Ws (row-major per o, stride 68: 16B-aligned rows, conflict-free pairs)
#pragma unroll
    for (int i = 0; i < 16; i++) {
        int idx = tid + i * 256;      // 4096 = 64*64
        int o = idx >> 6, c = idx & 63;
        bufB[o * 68 + c] = Wl[idx];
    }
    // X tile, float4-wide: 72 rows x 16 float4
    for (int q = tid; q < 72 * 16; q += 256) {
        int r = q >> 4, c4 = q & 15;
        int t = t0 + r - 4;
        float4 v = make_float4(0.f, 0.f, 0.f, 0.f);
        if (t >= 0 && t < 512)
            v = *(const float4*)(X + ((((size_t)n * 512 + t) * 64 + h) << 6) + c4 * 4);
        *(float4*)(bufA + r * 64 + c4 * 4) = v;
    }
    __syncthreads();

    int o = tid & 63;
    int tg = tid >> 6;                // 0..3

    // --- phase 1: support GEMM, paired over c (lane-pair partial dots) ---
    unsigned long long acc2[18];
#pragma unroll
    for (int j = 0; j < 18; j++) acc2[j] = 0ULL;
    for (int c4 = 0; c4 < 16; c4++) {
        ulonglong2 uw = *(const ulonglong2*)(bufB + o * 68 + c4 * 4);  // w pairs
#pragma unroll
        for (int j = 0; j < 18; j++) {
            ulonglong2 ux = *(const ulonglong2*)(bufA + (tg + 4 * j) * 64 + c4 * 4);
            FFMA2(acc2[j], ux.x, uw.x, acc2[j]);
            FFMA2(acc2[j], ux.y, uw.y, acc2[j]);
        }
    }

    float inv1 = g1[o] * rsqrtf(1.f + EPSF);
    float be1o = be1[o];
    float blo  = bl[o];
    float yreg[18];
#pragma unroll
    for (int j = 0; j < 18; j++) {
        int r = tg + 4 * j;           // covers 0..71
        int t = t0 + r - 4;
        float lo, hi;
        UNPACK2(lo, hi, acc2[j]);
        float accv = lo + hi;
        float yv = 0.f;
        if (t >= 0 && t < 512) {
            float d = g_diag[((size_t)n * 512 + t) * 64 + h];
            yv = fmaxf(d * (accv + blo) * inv1 + be1o, 0.f);
        }
        yreg[j] = yv;
    }
    __syncthreads();
    // y1 transposed + shifted copy (S[r] = y[r-1]); Ws region is dead now
#pragma unroll
    for (int j = 0; j < 18; j++) {
        int r = tg + 4 * j;
        bufA[o * 76 + r] = yreg[j];
        bufB[o * 76 + r + 1] = yreg[j];
    }
    if (tg == 0) bufB[o * 76] = 0.f;
    __syncthreads();

    // --- phase 2: temporal conv (K=9), t-paired accumulators ---
    int tl = tg * 16;
    unsigned long long acc[8];
#pragma unroll
    for (int p = 0; p < 8; p++) acc[p] = 0ULL;

    for (int op = 0; op < 64; op++) {
        // even-aligned v pairs: ve[m] = (v[2m], v[2m+1]), m=0..11
        unsigned long long ve[12];
        {
            const ulonglong2* vp = (const ulonglong2*)(bufA + op * 76 + tl);
#pragma unroll
            for (int q = 0; q < 6; q++) {
                ulonglong2 u = vp[q];
                ve[2 * q] = u.x;
                ve[2 * q + 1] = u.y;
            }
        }
        // odd-aligned v pairs from shifted copy: vo[m] = (v[2m+1], v[2m+2]), m=0..10
        unsigned long long vo[11];
#pragma unroll
        for (int m = 0; m < 11; m++)
            vo[m] = *(const unsigned long long*)(bufB + op * 76 + tl + 2 + 2 * m);

        const float2* wdp = g_Wd + (op * 9) * 64 + o;
        // even k: acc[p] += {w,w} * ve[p + k/2]
#pragma unroll
        for (int kk = 0; kk < 5; kk++) {
            unsigned long long w = *(const unsigned long long*)(wdp + (2 * kk) * 64);
#pragma unroll
            for (int p = 0; p < 8; p++) FFMA2(acc[p], ve[p + kk], w, acc[p]);
        }
        // odd k: acc[p] += {w,w} * vo[p + (k-1)/2]
#pragma unroll
        for (int kk = 0; kk < 4; kk++) {
            unsigned long long w = *(const unsigned long long*)(wdp + (2 * kk + 1) * 64);
#pragma unroll
            for (int p = 0; p < 8; p++) FFMA2(acc[p], vo[p + kk], w, acc[p]);
        }
    }

    float inv2 = g2[o] * rsqrtf(1.f + EPSF);
    float bet2 = be2[o] + bt[o] * inv2;
    size_t base = (((size_t)n * 512 + t0 + tl) * 64 + h) * 64 + o;
#pragma unroll
    for (int p = 0; p < 8; p++) {
        float lo, hi;
        UNPACK2(lo, hi, acc[p]);
        size_t i0 = base + (size_t)(2 * p) * 64 * 64;
        size_t i1 = base + (size_t)(2 * p + 1) * 64 * 64;
        out[i0] = fmaxf(lo * inv2 + bet2 + X[i0], 0.f);
        out[i1] = fmaxf(hi * inv2 + bet2 + X[i1], 0.f);
    }
}

// ---------------- launch ----------------
extern "C" void kernel_launch(void* const* d_in, const int* in_sizes, int n_in,
                              void* d_out, int out_size) {
    const float* X     = (const float*)d_in[0];
    const int*   eraw  = (const int*)d_in[1];
    const float* w1    = (const float*)d_in[2];
    const float* b1    = (const float*)d_in[3];
    const float* w2    = (const float*)d_in[4];
    const float* b2    = (const float*)d_in[5];
    const float* Wl    = (const float*)d_in[6];
    const float* bl    = (const float*)d_in[7];
    const float* bn1g  = (const float*)d_in[8];
    const float* bn1b  = (const float*)d_in[9];
    const float* Wtcn  = (const float*)d_in[10];
    const float* btcn  = (const float*)d_in[11];
    const float* bn2g  = (const float*)d_in[12];
    const float* bn2b  = (const float*)d_in[13];
    float* out = (float*)d_out;

    edge_decode_kernel<<<1, 1024>>>(eraw);
    wt_kernel<<<(64 * 9 * 64 + 255) / 256, 256>>>(Wtcn);
    diag_kernel<<<16 * 512, 64>>>(X, w1, b1, w2, b2);
    fused_kernel<<<16 * 64 * 8, 256>>>(X, Wl, bl, bn1g, bn1b,
                                       btcn, bn2g, bn2b, out);
}

// round 11
// speedup vs baseline: 1.0020x; 1.0020x over previous
#include <cuda_runtime.h>
#include <math.h>
#include <stdint.h>

#define EPSF 1e-5f

// packed fp32x2 FMA (SASS FFMA2) — only reachable via PTX
#define FFMA2(d,a,b,c) asm("fma.rn.f32x2 %0, %1, %2, %3;" \
                           : "=l"(d) : "l"(a), "l"(b), "l"(c))
#define UNPACK2(lo,hi,p) asm("mov.b64 {%0, %1}, %2;" : "=f"(lo), "=f"(hi) : "l"(p))

// ---------------- small scratch (no allocs allowed) ----------------
__device__ float  g_diag[16 * 512 * 64];   // (n,t,h)  2 MB
__device__ float2 g_Wd[64 * 9 * 64];       // dup'd conv weights [(op*9+k)*64+o] = {w,w}
__device__ int    g_eraw[16 * 512];        // decoded edges (n,2,e)  32 KB

// ---------------- kernel 0: dtype-robust edge decode (int32 OR int64) --------
__global__ void edge_decode_kernel(const int* __restrict__ raw) {
    int tid = threadIdx.x;                 // 1024 threads, 1 block
    int acc = 0;
    for (int i = tid; i < 4096; i += 1024) acc |= raw[2 * i + 1];
    int any_odd = __syncthreads_or(acc != 0);
    bool is64 = (any_odd == 0);
    for (int i = tid; i < 8192; i += 1024)
        g_eraw[i] = is64 ? raw[2 * i] : raw[i];
}

// ---------------- kernel 1: dup-pack W_tcn -> float2 [(op*9+k)][o] -----------
__global__ void wt_kernel(const float* __restrict__ W) {   // W[o][o'][k][1]
    int idx = blockIdx.x * blockDim.x + threadIdx.x;       // 64*9*64 = 36864
    if (idx >= 64 * 9 * 64) return;
    int o = idx & 63;
    int r = idx >> 6;           // op*9 + k
    int k = r % 9, op = r / 9;
    float w = W[(size_t)o * 576 + op * 9 + k];
    g_Wd[idx] = make_float2(w, w);
}

// ---------------- kernel 2: attention diag (edge-scan, atomic-free) ----------
__global__ void diag_kernel(const float* __restrict__ X,
                            const float* __restrict__ w1, const float* __restrict__ b1p,
                            const float* __restrict__ w2, const float* __restrict__ b2p) {
    int nt = blockIdx.x;          // 0..8191
    int n = nt >> 9;
    int h = threadIdx.x;

    __shared__ float sa1[64], sw1[64], sw2[64];
    __shared__ int   se[256];
    sw1[h] = w1[h];
    sw2[h] = w2[h];
    const int* ep = g_eraw + n * 512;
#pragma unroll
    for (int i = 0; i < 4; i++) {
        int e = h + i * 64;
        se[e] = ep[e] * 64 + ep[256 + e];
    }
    __syncthreads();

    const float4* xp = (const float4*)(X + ((size_t)nt * 64 + h) * 64);
    float d1 = 0.f, d2 = 0.f;
#pragma unroll
    for (int c4 = 0; c4 < 16; c4++) {
        float4 x = xp[c4];
        d1 += x.x * sw1[c4 * 4 + 0] + x.y * sw1[c4 * 4 + 1]
            + x.z * sw1[c4 * 4 + 2] + x.w * sw1[c4 * 4 + 3];
        d2 += x.x * sw2[c4 * 4 + 0] + x.y * sw2[c4 * 4 + 1]
            + x.z * sw2[c4 * 4 + 2] + x.w * sw2[c4 * 4 + 3];
    }
    sa1[h] = d1 + b1p[0];
    float a2h = d2 + b2p[0];
    __syncthreads();

    float den = 0.f;
#pragma unroll 8
    for (int k = 0; k < 64; k++) {
        float v = sa1[k] + a2h;
        v = (v > 0.f) ? v : 0.01f * v;
        den += __expf(v);
    }
    float num = 0.f;
    for (int i = 0; i < 256; i++) {
        int rc = se[i];
        if ((rc >> 6) == h) {
            float v = sa1[rc & 63] + a2h;
            v = (v > 0.f) ? v : 0.01f * v;
            num += __expf(v);
        }
    }
    g_diag[(size_t)nt * 64 + h] = num / den + 1.f;
}

// ---------------- kernel 3: FUSED support GEMM + bn1 + relu + temporal conv
//                  + bias + bn2 + residual + relu — packed f32x2 math ---------
// block: one (n,h) x a tile of 64 t's. 256 threads = 64 o x 4 t-groups.
// bufA: X tile [72 rows][64 ch]  ->  y1 transposed [64 o][76]
// bufB: Ws [64 o][68]            ->  S = y1 shifted by +1 row [64 o][76]
__global__ void __launch_bounds__(256, 3)
fused_kernel(const float* __restrict__ X,
             const float* __restrict__ Wl, const float* __restrict__ bl,
             const float* __restrict__ g1, const float* __restrict__ be1,
             const float* __restrict__ bt,
             const float* __restrict__ g2, const float* __restrict__ be2,
             float* __restrict__ out) {
    __shared__ float bufA[64 * 76];
    __shared__ float bufB[64 * 76];

    int bid = blockIdx.x;             // 0..8191
    int tb = bid & 7;
    int nh = bid >> 3;
    int n = nh >> 6, h = nh & 63;
    int t0 = tb * 64;
    int tid = threadIdx.x;

    // Ws (row-major per o, stride 68: 16B-aligned rows, conflict-free pairs)
#pragma unroll
    for (int i = 0; i < 16; i++) {
        int idx = tid + i * 256;      // 4096 = 64*64
        int o = idx >> 6, c = idx & 63;
        bufB[o * 68 + c] = Wl[idx];
    }
    // X tile, float4-wide: 72 rows x 16 float4
    for (int q = tid; q < 72 * 16; q += 256) {
        int r = q >> 4, c4 = q & 15;
        int t = t0 + r - 4;
        float4 v = make_float4(0.f, 0.f, 0.f, 0.f);
        if (t >= 0 && t < 512)
            v = *(const float4*)(X + ((((size_t)n * 512 + t) * 64 + h) << 6) + c4 * 4);
        *(float4*)(bufA + r * 64 + c4 * 4) = v;
    }
    __syncthreads();

    int o = tid & 63;
    int tg = tid >> 6;                // 0..3

    // --- phase 1: support GEMM, paired over c (lane-pair partial dots) ---
    unsigned long long acc2[18];
#pragma unroll
    for (int j = 0; j < 18; j++) acc2[j] = 0ULL;
    for (int c4 = 0; c4 < 16; c4++) {
        ulonglong2 uw = *(const ulonglong2*)(bufB + o * 68 + c4 * 4);  // w pairs
#pragma unroll
        for (int j = 0; j < 18; j++) {
            ulonglong2 ux = *(const ulonglong2*)(bufA + (tg + 4 * j) * 64 + c4 * 4);
            FFMA2(acc2[j], ux.x, uw.x, acc2[j]);
            FFMA2(acc2[j], ux.y, uw.y, acc2[j]);
        }
    }

    float inv1 = g1[o] * rsqrtf(1.f + EPSF);
    float be1o = be1[o];
    float blo  = bl[o];
    float yreg[18];
#pragma unroll
    for (int j = 0; j < 18; j++) {
        int r = tg + 4 * j;           // covers 0..71
        int t = t0 + r - 4;
        float lo, hi;
        UNPACK2(lo, hi, acc2[j]);
        float accv = lo + hi;
        float yv = 0.f;
        if (t >= 0 && t < 512) {
            float d = g_diag[((size_t)n * 512 + t) * 64 + h];
            yv = fmaxf(d * (accv + blo) * inv1 + be1o, 0.f);
        }
        yreg[j] = yv;
    }
    __syncthreads();
    // y1 transposed + shifted copy (S[r] = y[r-1]); Ws region is dead now
#pragma unroll
    for (int j = 0; j < 18; j++) {
        int r = tg + 4 * j;
        bufA[o * 76 + r] = yreg[j];
        bufB[o * 76 + r + 1] = yreg[j];
    }
    if (tg == 0) bufB[o * 76] = 0.f;
    __syncthreads();

    // --- phase 2: temporal conv (K=9), t-paired accumulators ---
    int tl = tg * 16;
    unsigned long long acc[8];
#pragma unroll
    for (int p = 0; p < 8; p++) acc[p] = 0ULL;

    for (int op = 0; op < 64; op++) {
        // even-aligned v pairs: ve[m] = (v[2m], v[2m+1]), m=0..11
        unsigned long long ve[12];
        {
            const ulonglong2* vp = (const ulonglong2*)(bufA + op * 76 + tl);
#pragma unroll
            for (int q = 0; q < 6; q++) {
                ulonglong2 u = vp[q];
                ve[2 * q] = u.x;
                ve[2 * q + 1] = u.y;
            }
        }
        // odd-aligned v pairs from shifted copy: vo[m] = (v[2m+1], v[2m+2]), m=0..10
        unsigned long long vo[11];
#pragma unroll
        for (int m = 0; m < 11; m++)
            vo[m] = *(const unsigned long long*)(bufB + op * 76 + tl + 2 + 2 * m);

        const float2* wdp = g_Wd + (op * 9) * 64 + o;
        // even k: acc[p] += {w,w} * ve[p + k/2]
#pragma unroll
        for (int kk = 0; kk < 5; kk++) {
            unsigned long long w = *(const unsigned long long*)(wdp + (2 * kk) * 64);
#pragma unroll
            for (int p = 0; p < 8; p++) FFMA2(acc[p], ve[p + kk], w, acc[p]);
        }
        // odd k: acc[p] += {w,w} * vo[p + (k-1)/2]
#pragma unroll
        for (int kk = 0; kk < 4; kk++) {
            unsigned long long w = *(const unsigned long long*)(wdp + (2 * kk + 1) * 64);
#pragma unroll
            for (int p = 0; p < 8; p++) FFMA2(acc[p], vo[p + kk], w, acc[p]);
        }
    }

    float inv2 = g2[o] * rsqrtf(1.f + EPSF);
    float bet2 = be2[o] + bt[o] * inv2;
    size_t base = (((size_t)n * 512 + t0 + tl) * 64 + h) * 64 + o;
#pragma unroll
    for (int p = 0; p < 8; p++) {
        float lo, hi;
        UNPACK2(lo, hi, acc[p]);
        size_t i0 = base + (size_t)(2 * p) * 64 * 64;
        size_t i1 = base + (size_t)(2 * p + 1) * 64 * 64;
        out[i0] = fmaxf(lo * inv2 + bet2 + X[i0], 0.f);
        out[i1] = fmaxf(hi * inv2 + bet2 + X[i1], 0.f);
    }
}

// ---------------- launch ----------------
extern "C" void kernel_launch(void* const* d_in, const int* in_sizes, int n_in,
                              void* d_out, int out_size) {
    const float* X     = (const float*)d_in[0];
    const int*   eraw  = (const int*)d_in[1];
    const float* w1    = (const float*)d_in[2];
    const float* b1    = (const float*)d_in[3];
    const float* w2    = (const float*)d_in[4];
    const float* b2    = (const float*)d_in[5];
    const float* Wl    = (const float*)d_in[6];
    const float* bl    = (const float*)d_in[7];
    const float* bn1g  = (const float*)d_in[8];
    const float* bn1b  = (const float*)d_in[9];
    const float* Wtcn  = (const float*)d_in[10];
    const float* btcn  = (const float*)d_in[11];
    const float* bn2g  = (const float*)d_in[12];
    const float* bn2b  = (const float*)d_in[13];
    float* out = (float*)d_out;

    edge_decode_kernel<<<1, 1024>>>(eraw);
    wt_kernel<<<(64 * 9 * 64 + 255) / 256, 256>>>(Wtcn);
    diag_kernel<<<16 * 512, 64>>>(X, w1, b1, w2, b2);
    fused_kernel<<<16 * 64 * 8, 256>>>(X, Wl, bl, bn1g, bn1b,
                                       btcn, bn2g, bn2b, out);
}

// round 14
// speedup vs baseline: 1.4608x; 1.4579x over previous
#include <cuda_runtime.h>
#include <cuda_bf16.h>
#include <math.h>
#include <stdint.h>

#define EPSF 1e-5f

__device__ float g_diag[16 * 512 * 64];
__device__ int   g_eraw[16 * 512];

// m16n8k16 bf16 MMA, fp32 accum (baseline PTX, maps to HMMA on sm_103)
#define MMA16816(c, a0,a1,a2,a3, b0,b1)                                   \
    asm volatile("mma.sync.aligned.m16n8k16.row.col.f32.bf16.bf16.f32 "   \
        "{%0,%1,%2,%3}, {%4,%5,%6,%7}, {%8,%9}, {%0,%1,%2,%3};"           \
        : "+f"((c)[0]), "+f"((c)[1]), "+f"((c)[2]), "+f"((c)[3])          \
        : "r"(a0), "r"(a1), "r"(a2), "r"(a3), "r"(b0), "r"(b1))

// bank-rotation swizzle: word (r, w) -> r*32 + ((w + 4r) & 31)
__device__ __forceinline__ int PW(int r, int w) { return r * 32 + ((w + 4 * r) & 31); }

// ---------------- kernel 0: dtype-robust edge decode ----------------
__global__ void edge_decode_kernel(const int* __restrict__ raw) {
    int tid = threadIdx.x;
    int acc = 0;
    for (int i = tid; i < 4096; i += 1024) acc |= raw[2 * i + 1];
    int any_odd = __syncthreads_or(acc != 0);
    bool is64 = (any_odd == 0);
    for (int i = tid; i < 8192; i += 1024)
        g_eraw[i] = is64 ? raw[2 * i] : raw[i];
}

// ---------------- kernel 1: attention diag ----------------
__global__ void diag_kernel(const float* __restrict__ X,
                            const float* __restrict__ w1, const float* __restrict__ b1p,
                            const float* __restrict__ w2, const float* __restrict__ b2p) {
    int nt = blockIdx.x;
    int n = nt >> 9;
    int h = threadIdx.x;
    __shared__ float sa1[64], sw1[64], sw2[64];
    __shared__ int   se[256];
    sw1[h] = w1[h];
    sw2[h] = w2[h];
    const int* ep = g_eraw + n * 512;
#pragma unroll
    for (int i = 0; i < 4; i++) { int e = h + i * 64; se[e] = ep[e] * 64 + ep[256 + e]; }
    __syncthreads();
    const float4* xp = (const float4*)(X + ((size_t)nt * 64 + h) * 64);
    float d1 = 0.f, d2 = 0.f;
#pragma unroll
    for (int c4 = 0; c4 < 16; c4++) {
        float4 x = xp[c4];
        d1 += x.x * sw1[c4 * 4] + x.y * sw1[c4 * 4 + 1] + x.z * sw1[c4 * 4 + 2] + x.w * sw1[c4 * 4 + 3];
        d2 += x.x * sw2[c4 * 4] + x.y * sw2[c4 * 4 + 1] + x.z * sw2[c4 * 4 + 2] + x.w * sw2[c4 * 4 + 3];
    }
    sa1[h] = d1 + b1p[0];
    float a2h = d2 + b2p[0];
    __syncthreads();
    float den = 0.f;
#pragma unroll 8
    for (int k = 0; k < 64; k++) {
        float v = sa1[k] + a2h;
        v = (v > 0.f) ? v : 0.01f * v;
        den += __expf(v);
    }
    float num = 0.f;
    for (int i = 0; i < 256; i++) {
        int rc = se[i];
        if ((rc >> 6) == h) {
            float v = sa1[rc & 63] + a2h;
            v = (v > 0.f) ? v : 0.01f * v;
            num += __expf(v);
        }
    }
    g_diag[(size_t)nt * 64 + h] = num / den + 1.f;
}

// ---------------- persistent fused kernel (mma.sync conv) ----------------
#define OFF_WH  0        // conv W hi: 9 taps x 64x64 bf16 (swizzled)  73728
#define OFF_WL  73728    // conv W lo                                   73728
#define OFF_YH  147456   // y1 hi: 136 x 64 bf16 (swizzled)            17408
#define OFF_YL  164864   // y1 lo                                       17408
#define OFF_X   182272   // X tile f32 136x64  /  D staging 128x68 f32  34816
#define OFF_DG  217088   // diag[136]                                     544
#define OFF_CON 217632   // inv1|be1|bl|inv2|bet2 (5x64 f32)             1280
#define SMEM_TOTAL 218912

__global__ void __launch_bounds__(512, 1)
fused_kernel(const float* __restrict__ X,
             const float* __restrict__ Wl, const float* __restrict__ bl,
             const float* __restrict__ g1, const float* __restrict__ be1,
             const float* __restrict__ Wt, const float* __restrict__ bt,
             const float* __restrict__ g2, const float* __restrict__ be2,
             float* __restrict__ out) {
    extern __shared__ char smem[];
    int tid = threadIdx.x, wid = tid >> 5, lane = tid & 31;
    float* sdg = (float*)(smem + OFF_DG);
    float* con = (float*)(smem + OFF_CON);

    // ---- prologue: pack conv weights hi/lo into swizzled smem ----
    for (int i = tid; i < 36864; i += 512) {
        int kk = i >> 12, rr = i & 4095, o = rr >> 6, op = rr & 63;
        float w = Wt[(size_t)o * 576 + op * 9 + kk];
        __nv_bfloat16 hi = __float2bfloat16(w);
        __nv_bfloat16 lo = __float2bfloat16(w - __bfloat162float(hi));
        int pw = PW(o, op >> 1);
        ((__nv_bfloat16*)(smem + OFF_WH + kk * 8192))[pw * 2 + (op & 1)] = hi;
        ((__nv_bfloat16*)(smem + OFF_WL + kk * 8192))[pw * 2 + (op & 1)] = lo;
    }
    if (tid < 64) {
        float i1 = g1[tid] * rsqrtf(1.f + EPSF);
        float i2 = g2[tid] * rsqrtf(1.f + EPSF);
        con[tid] = i1; con[64 + tid] = be1[tid]; con[128 + tid] = bl[tid];
        con[192 + tid] = i2; con[256 + tid] = be2[tid] + bt[tid] * i2;
    }
    __syncthreads();

    int o = tid & 63, tg = tid >> 6;      // support mapping: 8 row-groups
    const float4* Xg = (const float4*)X;
    const float4* Wl4 = (const float4*)Wl;   // W_lin (O,C) row-major

    for (int item = blockIdx.x; item < 4096; item += gridDim.x) {
        int n = item >> 8, rem = item & 255, h = rem >> 2, t0 = (rem & 3) << 7;

        // ---- load X tile (136 rows x 64 f32) + diag ----
        float4* Xb = (float4*)(smem + OFF_X);
        for (int q = tid; q < 136 * 16; q += 512) {
            int r = q >> 4, c4 = q & 15, t = t0 - 4 + r;
            float4 v = make_float4(0.f, 0.f, 0.f, 0.f);
            if ((unsigned)t < 512u) v = Xg[(((size_t)n * 512 + t) * 64 + h) * 16 + c4];
            Xb[r * 16 + c4] = v;
        }
        for (int q = tid; q < 136; q += 512) {
            int t = t0 - 4 + q;
            sdg[q] = ((unsigned)t < 512u) ? g_diag[((size_t)n * 512 + t) * 64 + h] : 0.f;
        }
        __syncthreads();

        // ---- scalar support GEMM + diag + bn1 + relu ----
        // acc[o] = sum_c X[r][c] * W_lin[o][c]; thread owns output channel o.
        float acc[17];
#pragma unroll
        for (int j = 0; j < 17; j++) acc[j] = 0.f;
#pragma unroll
        for (int c4 = 0; c4 < 16; c4++) {
            float4 wv = __ldg(Wl4 + o * 16 + c4);   // row o, cols 4c4..4c4+3 (L1-hot)
#pragma unroll
            for (int j = 0; j < 17; j++) {
                float4 x = Xb[(tg + 8 * j) * 16 + c4];
                acc[j] += x.x * wv.x + x.y * wv.y + x.z * wv.z + x.w * wv.w;
            }
        }
        float i1 = con[o], b1v = con[64 + o], blv = con[128 + o];
#pragma unroll
        for (int j = 0; j < 17; j++) {
            int r = tg + 8 * j, t = t0 - 4 + r;
            float yv = 0.f;
            if ((unsigned)t < 512u)
                yv = fmaxf(sdg[r] * (acc[j] + blv) * i1 + b1v, 0.f);
            acc[j] = yv;
        }
        // ---- write y1 hi/lo (swizzled bf16) ----
#pragma unroll
        for (int j = 0; j < 17; j++) {
            int r = tg + 8 * j;
            __nv_bfloat16 hi = __float2bfloat16(acc[j]);
            __nv_bfloat16 lo = __float2bfloat16(acc[j] - __bfloat162float(hi));
            int pw = PW(r, o >> 1);
            ((__nv_bfloat16*)(smem + OFF_YH))[pw * 2 + (o & 1)] = hi;
            ((__nv_bfloat16*)(smem + OFF_YL))[pw * 2 + (o & 1)] = lo;
        }
        __syncthreads();   // y1 complete; X reads complete

        // ---- conv: 9 taps x 4 k-chunks, 3-pass bf16 mma ----
        {
            int ms = wid >> 1, nh = wid & 1;          // m-stripe, n-half
            int lr = lane >> 2, lc = lane & 3;
            float C0[4], C1[4], C2[4], C3[4];
#pragma unroll
            for (int q = 0; q < 4; q++) { C0[q] = 0.f; C1[q] = 0.f; C2[q] = 0.f; C3[q] = 0.f; }
            float* Cn[4] = {C0, C1, C2, C3};
            const uint32_t* YH = (const uint32_t*)(smem + OFF_YH);
            const uint32_t* YL = (const uint32_t*)(smem + OFF_YL);
#pragma unroll 1
            for (int kk = 0; kk < 9; kk++) {
                const uint32_t* BH = (const uint32_t*)(smem + OFF_WH + kk * 8192);
                const uint32_t* BL = (const uint32_t*)(smem + OFF_WL + kk * 8192);
                int r0 = 16 * ms + kk + lr;
#pragma unroll
                for (int kc = 0; kc < 4; kc++) {
                    int w0 = 8 * kc + lc;
                    uint32_t a0h = YH[PW(r0, w0)],     a1h = YH[PW(r0 + 8, w0)];
                    uint32_t a2h = YH[PW(r0, w0 + 4)], a3h = YH[PW(r0 + 8, w0 + 4)];
                    uint32_t a0l = YL[PW(r0, w0)],     a1l = YL[PW(r0 + 8, w0)];
                    uint32_t a2l = YL[PW(r0, w0 + 4)], a3l = YL[PW(r0 + 8, w0 + 4)];
#pragma unroll
                    for (int nt = 0; nt < 4; nt++) {
                        int nn = 32 * nh + 8 * nt + lr;
                        uint32_t b0h = BH[PW(nn, w0)], b1h = BH[PW(nn, w0 + 4)];
                        uint32_t b0l = BL[PW(nn, w0)], b1l = BL[PW(nn, w0 + 4)];
                        MMA16816(Cn[nt], a0h, a1h, a2h, a3h, b0h, b1h);
                        MMA16816(Cn[nt], a0h, a1h, a2h, a3h, b0l, b1l);
                        MMA16816(Cn[nt], a0l, a1l, a2l, a3l, b0h, b1h);
                    }
                }
            }
            // stage D to smem (reuse X region), stride 68 f32
            float* Dst = (float*)(smem + OFF_X);
#pragma unroll
            for (int nt = 0; nt < 4; nt++) {
                int col = 32 * nh + 8 * nt + 2 * lc;
                int row = 16 * ms + lr;
                Dst[row * 68 + col]           = Cn[nt][0];
                Dst[row * 68 + col + 1]       = Cn[nt][1];
                Dst[(row + 8) * 68 + col]     = Cn[nt][2];
                Dst[(row + 8) * 68 + col + 1] = Cn[nt][3];
            }
        }
        __syncthreads();

        // ---- epilogue: bn2 + residual + relu, coalesced float4 stores ----
        {
            const float* Dst = (const float*)(smem + OFF_X);
#pragma unroll
            for (int i = 0; i < 4; i++) {
                int idx = tid + i * 512;
                int row = idx >> 4, c4 = idx & 15;
                float4 dv = *(const float4*)(Dst + row * 68 + 4 * c4);
                size_t gi = (((size_t)n * 512 + t0 + row) * 64 + h) * 16 + c4;
                float4 xv = Xg[gi];
                float4 iv = *(const float4*)(con + 192 + 4 * c4);
                float4 bv = *(const float4*)(con + 256 + 4 * c4);
                float4 rv;
                rv.x = fmaxf(dv.x * iv.x + bv.x + xv.x, 0.f);
                rv.y = fmaxf(dv.y * iv.y + bv.y + xv.y, 0.f);
                rv.z = fmaxf(dv.z * iv.z + bv.z + xv.z, 0.f);
                rv.w = fmaxf(dv.w * iv.w + bv.w + xv.w, 0.f);
                ((float4*)out)[gi] = rv;
            }
        }
        __syncthreads();   // protect smem before next tile overwrites
    }
}

// ---------------- launch ----------------
extern "C" void kernel_launch(void* const* d_in, const int* in_sizes, int n_in,
                              void* d_out, int out_size) {
    const float* X    = (const float*)d_in[0];
    const int*   eraw = (const int*)d_in[1];
    const float* w1   = (const float*)d_in[2];
    const float* b1   = (const float*)d_in[3];
    const float* w2   = (const float*)d_in[4];
    const float* b2   = (const float*)d_in[5];
    const float* Wl   = (const float*)d_in[6];
    const float* bl   = (const float*)d_in[7];
    const float* bn1g = (const float*)d_in[8];
    const float* bn1b = (const float*)d_in[9];
    const float* Wtcn = (const float*)d_in[10];
    const float* btcn = (const float*)d_in[11];
    const float* bn2g = (const float*)d_in[12];
    const float* bn2b = (const float*)d_in[13];
    float* out = (float*)d_out;

    cudaFuncSetAttribute(fused_kernel, cudaFuncAttributeMaxDynamicSharedMemorySize, SMEM_TOTAL);
    edge_decode_kernel<<<1, 1024>>>(eraw);
    diag_kernel<<<16 * 512, 64>>>(X, w1, b1, w2, b2);
    fused_kernel<<<148, 512, SMEM_TOTAL>>>(X, Wl, bl, bn1g, bn1b,
                                           Wtcn, btcn, bn2g, bn2b, out);
}